// round 13
// baseline (speedup 1.0000x reference)
#include <cuda_runtime.h>
#include <math.h>

// ---------------- problem constants ----------------
#define BB   32
#define TT   4096
#define AD   128
#define SS   100
#define BDM  10
#define HH   50
#define DD   30
#define CH   64            // chunk = 64 timesteps
#define NCH  (TT / CH)     // 64 chunks
#define NQ   25            // S/4 float4 "quads"
#define TROW 65            // padded tile row (float4)
#define BTROW 132          // bts words per 32-step group
#define NGRP (TT / 32)     // 128 groups
#define FULLM 0xffffffffu

// ---------------- global scratch ----------------
__device__ __align__(16) float g_z[(size_t)BB * TT * BDM];

// =====================================================================
// Kernel 1: z = mlp(x) only (sims GEMM moved into k_dp producers)
// =====================================================================
__global__ void k_project(const float* __restrict__ x,
                          const float* __restrict__ w1, const float* __restrict__ b1,
                          const float* __restrict__ w2, const float* __restrict__ b2,
                          const float* __restrict__ w3, const float* __restrict__ b3)
{
    __shared__ float w1s[BDM * AD];
    __shared__ float w2s[BDM * BDM], w3s[BDM * BDM];
    __shared__ float b1s[BDM], b2s[BDM], b3s[BDM];

    int tid = threadIdx.x;
    for (int i = tid; i < BDM * AD; i += 256) w1s[i] = w1[i];
    if (tid < BDM * BDM) { w2s[tid] = w2[tid]; w3s[tid] = w3[tid]; }
    if (tid < BDM) { b1s[tid] = b1[tid]; b2s[tid] = b2[tid]; b3s[tid] = b3[tid]; }
    __syncthreads();

    int gtid = blockIdx.x * 256 + tid;         // b*T + t
    const float4* xr = (const float4*)(x + (size_t)gtid * AD);

    float z1[BDM];
#pragma unroll
    for (int d = 0; d < BDM; d++) z1[d] = b1s[d];

#pragma unroll 8
    for (int kk = 0; kk < AD / 4; ++kk) {
        float4 xv = xr[kk];
#pragma unroll
        for (int d = 0; d < BDM; d++) {
            float4 wv = ((const float4*)w1s)[d * (AD / 4) + kk];
            z1[d] += xv.x * wv.x + xv.y * wv.y + xv.z * wv.z + xv.w * wv.w;
        }
    }
#pragma unroll
    for (int d = 0; d < BDM; d++) z1[d] = fmaxf(z1[d], 0.0f);

    float z2[BDM];
#pragma unroll
    for (int d = 0; d < BDM; d++) {
        float a = b2s[d];
#pragma unroll
        for (int e = 0; e < BDM; e++) a += z1[e] * w2s[d * BDM + e];
        z2[d] = fmaxf(a, 0.0f);
    }
    float* zo = g_z + (size_t)gtid * BDM;
#pragma unroll
    for (int d = 0; d < BDM; d++) {
        float a = b3s[d];
#pragma unroll
        for (int e = 0; e < BDM; e++) a += z2[e] * w3s[d * BDM + e];
        zo[d] = a;
    }
}

// =====================================================================
// Kernel 2: warp0 consumer (R10 exact), warps1-7 producers now COMPUTE
// sims = z @ c for the next chunk directly into the smem tile.
// bts: 1 bit/state/step; group g = t in [32g,32g+31]; lane owns states
// 4L..4L+3; word (g*BTROW + lane*4 + i), bit position 31-(t&31).
// =====================================================================
struct SmemB {
    float4 tile[2][NQ * TROW];       // 52,000 B
    unsigned int bts[NGRP * BTROW];  // 67,584 B
    float4 cq[BDM * NQ];             //  4,000 B  c as [d][q] float4
    float zstage[CH * BDM];          //  2,560 B
    float zz[SS * BDM];
    int bound[SS + 4];
    float hbuf[HH], cbuf[HH], gates[4 * HH];
    float rbuf[32], r2buf[32];
};

__device__ __forceinline__ float sigm(float v) { return 1.0f / (1.0f + __expf(-v)); }

// producers (224 threads, p = tid-32 in [0,224)): load z chunk, GEMM to tile
__device__ __forceinline__ void produce_chunk(SmemB* sm, const float* __restrict__ zsrc,
                                              int p, int cn)
{
    // stage z: 640 consecutive floats (coalesced)
    const float* zg = zsrc + (size_t)cn * CH * BDM;
    if (p < CH * BDM) sm->zstage[p] = zg[p];        // 640 < 224*3
    for (int i = p + 224; i < CH * BDM; i += 224) sm->zstage[i] = zg[i];
    asm volatile("bar.sync 1, 224;" ::: "memory");

    // sims GEMM: 1600 float4 outputs
    float4* dst = sm->tile[cn & 1];
    for (int i = p; i < CH * NQ; i += 224) {
        int tr = i / NQ;
        int q  = i - tr * NQ;
        const float* zr = sm->zstage + tr * BDM;
        float4 a = make_float4(0.f, 0.f, 0.f, 0.f);
#pragma unroll
        for (int d = 0; d < BDM; d++) {
            float zv = zr[d];
            float4 cv = sm->cq[d * NQ + q];
            a.x += zv * cv.x; a.y += zv * cv.y;
            a.z += zv * cv.z; a.w += zv * cv.w;
        }
        dst[q * TROW + tr] = a;
    }
}

// one DP step; U = t&31 compile-time (R10 exact)
#define DPSTEP3(sv, U) do {                                                      \
    float n3 = fmaxf(st2, st3) + (sv).w;                                         \
    float nsh = __shfl_up_sync(FULLM, n3, 1);                                    \
    float left = (lane == 0) ? 0.0f : left_next;                                 \
    float d1 = st1 - st0;                                                        \
    float d2 = st2 - st1;                                                        \
    float d3 = st3 - st2;                                                        \
    float n1 = fmaxf(st0, st1) + (sv).y;                                         \
    float n2 = fmaxf(st1, st2) + (sv).z;                                         \
    acc1 |= (__float_as_uint(d1) >> (U)) & (1u << (31 - (U)));                   \
    acc2 |= (__float_as_uint(d2) >> (U)) & (1u << (31 - (U)));                   \
    acc3 |= (__float_as_uint(d3) >> (U)) & (1u << (31 - (U)));                   \
    float d0 = st0 - left;                                                       \
    float n0 = fmaxf(left, st0) + (sv).x;                                        \
    acc0 |= (__float_as_uint(d0) >> (U)) & (1u << (31 - (U)));                   \
    st0 = n0; st1 = n1; st2 = n2; st3 = n3; left_next = nsh; } while (0)

__global__ void __launch_bounds__(256, 1)
k_dp(const float* __restrict__ c,
     const float* __restrict__ w_ih, const float* __restrict__ w_hh,
     const float* __restrict__ b_ih, const float* __restrict__ b_hh,
     const float* __restrict__ wr1, const float* __restrict__ br1,
     const float* __restrict__ wr2, const float* __restrict__ br2,
     const float* __restrict__ wr3, const float* __restrict__ br3,
     float* __restrict__ out)
{
    extern __shared__ unsigned char smraw[];
    SmemB* sm = reinterpret_cast<SmemB*>(smraw);

    const int tid = threadIdx.x;
    const int b = blockIdx.x;
    const int lane = tid & 31;
    const float* zsrc = g_z + (size_t)b * TT * BDM;

    // ---- prologue ----
    if (tid < 32) {
        for (int i = lane; i < SS * BDM; i += 32) sm->zz[i] = 0.0f;
        for (int i = lane; i < HH; i += 32) { sm->hbuf[i] = 0.0f; sm->cbuf[i] = 0.0f; }
    } else {
        int p = tid - 32;
        // stage c as float4 [d][q]
        for (int i = p; i < BDM * NQ; i += 224)
            sm->cq[i] = ((const float4*)c)[i];
        asm volatile("bar.sync 1, 224;" ::: "memory");
        produce_chunk(sm, zsrc, p, 0);
    }
    __syncthreads();

    // ---- DP state ----
    const int qln = lane < NQ ? lane : NQ - 1;
    float st0 = 0.f, st1 = 0.f, st2 = 0.f, st3 = 0.f, left_next = 0.f;

    for (int ci = 0; ci < NCH; ++ci) {
        if (tid < 32) {
            const float4* tb = sm->tile[ci & 1] + qln * TROW;
            unsigned acc0, acc1, acc2, acc3;
            if (ci == 0) {
                acc0 = acc1 = acc2 = acc3 = 0;
                {
                    float4 sv = tb[0];
                    st0 = sv.x; st1 = sv.y; st2 = sv.z; st3 = sv.w;
                    left_next = __shfl_up_sync(FULLM, st3, 1);
                }
#pragma unroll
                for (int u = 1; u < 32; ++u) DPSTEP3(tb[u], u);
                *(uint4*)&sm->bts[0 * BTROW + lane * 4] =
                    make_uint4(acc0, acc1, acc2, acc3);
                acc0 = acc1 = acc2 = acc3 = 0;
#pragma unroll
                for (int u = 0; u < 32; ++u) DPSTEP3(tb[32 + u], u);
                *(uint4*)&sm->bts[1 * BTROW + lane * 4] =
                    make_uint4(acc0, acc1, acc2, acc3);
            } else {
#pragma unroll 1
                for (int g2 = 0; g2 < 2; ++g2) {
                    acc0 = acc1 = acc2 = acc3 = 0;
                    const float4* tg = tb + g2 * 32;
#pragma unroll
                    for (int u = 0; u < 32; ++u) DPSTEP3(tg[u], u);
                    *(uint4*)&sm->bts[(ci * 2 + g2) * BTROW + lane * 4] =
                        make_uint4(acc0, acc1, acc2, acc3);
                }
            }
        } else {
            if (ci + 1 < NCH) produce_chunk(sm, zsrc, tid - 32, ci + 1);
        }
        __syncthreads();
    }

    // ---------------- warp-parallel backtrack ----------------
    if (tid < 32) {
        int s = SS - 1, cur = TT - 1;
        while (s > 0) {
            int col4 = (s >> 2) * 4 + (s & 3);
            int gtop = cur >> 5;
            int ttstar = 0;
            for (int gb = gtop - 31; ; gb -= 32) {
                int g = gb + lane;
                unsigned w = 0;
                if (g >= 0 && g <= gtop) {
                    w = sm->bts[g * BTROW + col4];
                    if (g == gtop) {
                        int pm = cur & 31;
                        w &= ~((1u << (31 - pm)) - 1u);
                    }
                }
                unsigned bal = __ballot_sync(FULLM, w != 0);
                if (bal) {
                    int hl = 31 - __clz((int)bal);
                    unsigned wh = __shfl_sync(FULLM, w, hl);
                    int pos = __ffs((int)wh) - 1;
                    ttstar = (gb + hl) * 32 + (31 - pos);
                    break;
                }
                if (gb <= 0 || gb * 32 <= s + 1) break;
            }
            int ttd = ttstar > s ? ttstar : s;
            if (lane == 0) sm->bound[s] = ttd;
            cur = ttd - 1;
            s--;
        }
        if (lane == 0) { sm->bound[0] = 0; sm->bound[SS] = TT; }
    }
    __syncthreads();

    // ---------------- segment sums ----------------
    {
        const int t0 = tid * (TT / 256);
        int lo = 0, hi = SS - 1;
        while (lo < hi) {
            int mid = (lo + hi + 1) >> 1;
            if (sm->bound[mid] <= t0) lo = mid; else hi = mid - 1;
        }
        int s = lo;
        int nxtb = sm->bound[s + 1];
        const float* zb = zsrc + (size_t)t0 * BDM;
        float av[BDM];
#pragma unroll
        for (int d = 0; d < BDM; d++) av[d] = 0.0f;

        for (int kk = 0; kk < TT / 256; ++kk) {
            int t = t0 + kk;
            if (t >= nxtb) {
#pragma unroll
                for (int d = 0; d < BDM; d++) {
                    atomicAdd(&sm->zz[s * BDM + d], av[d]);
                    av[d] = 0.0f;
                }
                s++;
                nxtb = sm->bound[s + 1];
            }
#pragma unroll
            for (int d = 0; d < BDM; d++) av[d] += zb[kk * BDM + d];
        }
#pragma unroll
        for (int d = 0; d < BDM; d++) atomicAdd(&sm->zz[s * BDM + d], av[d]);
    }
    __syncthreads();

    for (int i = tid; i < SS * BDM; i += 256) {
        int s = i / BDM;
        sm->zz[i] = sm->zz[i] / (float)(sm->bound[s + 1] - sm->bound[s]);
    }
    __syncthreads();

    // ---------------- LSTM (weights in registers) ----------------
    float whr[HH], wir[BDM], bsr = 0.0f;
    if (tid < 4 * HH) {
#pragma unroll
        for (int kk = 0; kk < HH; kk++) whr[kk] = w_hh[tid * HH + kk];
#pragma unroll
        for (int d = 0; d < BDM; d++) wir[d] = w_ih[tid * BDM + d];
        bsr = b_ih[tid] + b_hh[tid];
    }

    for (int stp = 0; stp < SS; ++stp) {
        if (tid < 4 * HH) {
            float g = bsr;
            const float* xt = sm->zz + stp * BDM;
#pragma unroll
            for (int d = 0; d < BDM; d++) g += wir[d] * xt[d];
#pragma unroll
            for (int kk = 0; kk < HH; kk++) g += whr[kk] * sm->hbuf[kk];
            sm->gates[tid] = g;
        }
        __syncthreads();
        if (tid < HH) {
            float iv = sm->gates[tid];
            float fv = sm->gates[HH + tid];
            float gv = sm->gates[2 * HH + tid];
            float ov = sm->gates[3 * HH + tid];
            float cc = sigm(fv) * sm->cbuf[tid] + sigm(iv) * tanhf(gv);
            sm->cbuf[tid] = cc;
            sm->hbuf[tid] = sigm(ov) * tanhf(cc);
        }
        __syncthreads();
    }

    // ---------------- MLP head ----------------
    if (tid < DD) {
        float r = br1[tid];
#pragma unroll 10
        for (int kk = 0; kk < HH; kk++) r += wr1[tid * HH + kk] * sm->hbuf[kk];
        sm->rbuf[tid] = fmaxf(r, 0.0f);
    }
    __syncthreads();
    if (tid < DD) {
        float r = br2[tid];
#pragma unroll
        for (int kk = 0; kk < DD; kk++) r += wr2[tid * DD + kk] * sm->rbuf[kk];
        sm->r2buf[tid] = fmaxf(r, 0.0f);
    }
    __syncthreads();
    if (tid == 0) {
        float r = br3[0];
#pragma unroll
        for (int d = 0; d < DD; d++) r += wr3[d] * sm->r2buf[d];
        out[b] = r;
    }
}

// =====================================================================
// launch
// =====================================================================
extern "C" void kernel_launch(void* const* d_in, const int* in_sizes, int n_in,
                              void* d_out, int out_size)
{
    (void)in_sizes; (void)n_in; (void)out_size;
    const float* x    = (const float*)d_in[0];
    const float* c    = (const float*)d_in[1];
    const float* w1   = (const float*)d_in[2];
    const float* b1   = (const float*)d_in[3];
    const float* w2   = (const float*)d_in[4];
    const float* b2   = (const float*)d_in[5];
    const float* w3   = (const float*)d_in[6];
    const float* b3   = (const float*)d_in[7];
    const float* w_ih = (const float*)d_in[8];
    const float* w_hh = (const float*)d_in[9];
    const float* b_ih = (const float*)d_in[10];
    const float* b_hh = (const float*)d_in[11];
    const float* wr1  = (const float*)d_in[12];
    const float* br1  = (const float*)d_in[13];
    const float* wr2  = (const float*)d_in[14];
    const float* br2  = (const float*)d_in[15];
    const float* wr3  = (const float*)d_in[16];
    const float* br3  = (const float*)d_in[17];
    float* out = (float*)d_out;

    cudaFuncSetAttribute(k_dp, cudaFuncAttributeMaxDynamicSharedMemorySize,
                         (int)sizeof(SmemB));

    k_project<<<(BB * TT) / 256, 256>>>(x, w1, b1, w2, b2, w3, b3);
    k_dp<<<BB, 256, sizeof(SmemB)>>>(c, w_ih, w_hh, b_ih, b_hh,
                                     wr1, br1, wr2, br2, wr3, br3, out);
}

// round 14
// speedup vs baseline: 1.2676x; 1.2676x over previous
#include <cuda_runtime.h>
#include <math.h>

// ---------------- problem constants ----------------
#define BB   32
#define TT   4096
#define AD   128
#define SS   100
#define BDM  10
#define HH   50
#define DD   30
#define CH   64            // chunk = 64 timesteps (k_dp1 pipeline)
#define NCH  (TT / CH)     // 64 chunks
#define NQ   25            // S/4 float4 "quads"
#define TROW 65            // padded tile row (float4) in k_dp1
#define GR   32            // group = 32 steps (bit granularity)
#define NGRP (TT / GR)     // 128 groups
#define BTROW 132          // bts words per group (100 used, padded)
#define GPW  8             // groups per CTA in k_dp2
#define FULLM 0xffffffffu

// ---------------- global scratch ----------------
__device__ __align__(16) float4 g_simsT[(size_t)BB * NQ * TT];        // [b][q][t]
__device__ __align__(16) float  g_z[(size_t)BB * TT * BDM];
__device__ __align__(16) float  g_bnd[(size_t)BB * NGRP * SS];        // boundary vectors
__device__ __align__(16) unsigned int g_bts[(size_t)BB * NGRP * BTROW];

// =====================================================================
// Kernel 1: z = mlp(x); sims stored quad-transposed [b][q][t]
// =====================================================================
__global__ void k_project(const float* __restrict__ x, const float* __restrict__ c,
                          const float* __restrict__ w1, const float* __restrict__ b1,
                          const float* __restrict__ w2, const float* __restrict__ b2,
                          const float* __restrict__ w3, const float* __restrict__ b3)
{
    __shared__ float w1s[BDM * AD];
    __shared__ float cs[BDM * SS];
    __shared__ float w2s[BDM * BDM], w3s[BDM * BDM];
    __shared__ float b1s[BDM], b2s[BDM], b3s[BDM];

    int tid = threadIdx.x;
    for (int i = tid; i < BDM * AD; i += 256) w1s[i] = w1[i];
    for (int i = tid; i < BDM * SS; i += 256) cs[i] = c[i];
    if (tid < BDM * BDM) { w2s[tid] = w2[tid]; w3s[tid] = w3[tid]; }
    if (tid < BDM) { b1s[tid] = b1[tid]; b2s[tid] = b2[tid]; b3s[tid] = b3[tid]; }
    __syncthreads();

    int gtid = blockIdx.x * 256 + tid;         // b*T + t
    int b = gtid >> 12;
    int t = gtid & (TT - 1);
    const float4* xr = (const float4*)(x + (size_t)gtid * AD);

    float z1[BDM];
#pragma unroll
    for (int d = 0; d < BDM; d++) z1[d] = b1s[d];

#pragma unroll 8
    for (int kk = 0; kk < AD / 4; ++kk) {
        float4 xv = xr[kk];
#pragma unroll
        for (int d = 0; d < BDM; d++) {
            float4 wv = ((const float4*)w1s)[d * (AD / 4) + kk];
            z1[d] += xv.x * wv.x + xv.y * wv.y + xv.z * wv.z + xv.w * wv.w;
        }
    }
#pragma unroll
    for (int d = 0; d < BDM; d++) z1[d] = fmaxf(z1[d], 0.0f);

    float z2[BDM];
#pragma unroll
    for (int d = 0; d < BDM; d++) {
        float a = b2s[d];
#pragma unroll
        for (int e = 0; e < BDM; e++) a += z1[e] * w2s[d * BDM + e];
        z2[d] = fmaxf(a, 0.0f);
    }
    float z3[BDM];
#pragma unroll
    for (int d = 0; d < BDM; d++) {
        float a = b3s[d];
#pragma unroll
        for (int e = 0; e < BDM; e++) a += z2[e] * w3s[d * BDM + e];
        z3[d] = a;
    }

    float* zo = g_z + (size_t)gtid * BDM;
#pragma unroll
    for (int d = 0; d < BDM; d++) zo[d] = z3[d];

#pragma unroll
    for (int q = 0; q < NQ; ++q) {
        float4 a = make_float4(0.f, 0.f, 0.f, 0.f);
#pragma unroll
        for (int d = 0; d < BDM; d++) {
            float zv = z3[d];
            float4 cv = ((const float4*)cs)[d * NQ + q];
            a.x += zv * cv.x; a.y += zv * cv.y;
            a.z += zv * cv.z; a.w += zv * cv.w;
        }
        g_simsT[((size_t)b * NQ + q) * TT + t] = a;   // coalesced over t
    }
}

// =====================================================================
// helpers
// =====================================================================
__device__ __forceinline__ float sigm(float v) { return 1.0f / (1.0f + __expf(-v)); }

__device__ __forceinline__ unsigned smem_u32(const void* p)
{
    return (unsigned)__cvta_generic_to_shared(p);
}

// =====================================================================
// Kernel 2a (k_dp1): slim forward DP (NO bits), stores boundary vectors
// every 32 steps. warp0 consumer, warps1-7 cp.async producers (R10).
// =====================================================================
struct SmemD {
    float4 tile[2][NQ * TROW];     // 52,000 B
};

__device__ __forceinline__ void copy_chunk_async(SmemD* sm, int b, int p, int cn)
{
    if (p < 200) {
        float4* dst = sm->tile[cn & 1];
        const float4* src = g_simsT + (size_t)b * NQ * TT + (size_t)cn * CH;
#pragma unroll
        for (int k = 0; k < 8; k++) {
            int i = p + k * 200;
            int q = i >> 6;
            int r = i & 63;
            unsigned d = smem_u32(dst + q * TROW + r);
            const float4* g = src + (size_t)q * TT + r;
            asm volatile("cp.async.cg.shared.global [%0], [%1], 16;"
                         :: "r"(d), "l"(g) : "memory");
        }
        asm volatile("cp.async.commit_group;" ::: "memory");
        asm volatile("cp.async.wait_group 0;" ::: "memory");
    }
}

// slim step: no bit packing
#define DPSLIM(sv) do {                                                          \
    float n3 = fmaxf(st2, st3) + (sv).w;                                         \
    float nsh = __shfl_up_sync(FULLM, n3, 1);                                    \
    float left = (lane == 0) ? 0.0f : left_next;                                 \
    float n1 = fmaxf(st0, st1) + (sv).y;                                         \
    float n2 = fmaxf(st1, st2) + (sv).z;                                         \
    float n0 = fmaxf(left, st0) + (sv).x;                                        \
    st0 = n0; st1 = n1; st2 = n2; st3 = n3; left_next = nsh; } while (0)

__global__ void __launch_bounds__(256, 1)
k_dp1()
{
    extern __shared__ unsigned char smraw[];
    SmemD* sm = reinterpret_cast<SmemD*>(smraw);

    const int tid = threadIdx.x;
    const int b = blockIdx.x;
    const int lane = tid & 31;

    if (tid >= 32) copy_chunk_async(sm, b, tid - 32, 0);
    __syncthreads();

    const int qln = lane < NQ ? lane : NQ - 1;
    float st0 = 0.f, st1 = 0.f, st2 = 0.f, st3 = 0.f, left_next = 0.f;

    for (int ci = 0; ci < NCH; ++ci) {
        if (tid < 32) {
            const float4* tb = sm->tile[ci & 1] + qln * TROW;
            if (ci == 0) {
                {
                    float4 sv = tb[0];
                    st0 = sv.x; st1 = sv.y; st2 = sv.z; st3 = sv.w;
                    left_next = __shfl_up_sync(FULLM, st3, 1);
                }
#pragma unroll
                for (int u = 1; u < 32; ++u) DPSLIM(tb[u]);
                if (lane < NQ)
                    *(float4*)&g_bnd[((size_t)b * NGRP + 1) * SS + 4 * lane] =
                        make_float4(st0, st1, st2, st3);
#pragma unroll
                for (int u = 32; u < 64; ++u) DPSLIM(tb[u]);
                if (lane < NQ)
                    *(float4*)&g_bnd[((size_t)b * NGRP + 2) * SS + 4 * lane] =
                        make_float4(st0, st1, st2, st3);
            } else {
#pragma unroll 1
                for (int g2 = 0; g2 < 2; ++g2) {
                    const float4* tg = tb + g2 * 32;
#pragma unroll
                    for (int u = 0; u < 32; ++u) DPSLIM(tg[u]);
                    int g = 2 * ci + g2 + 1;
                    if (g < NGRP && lane < NQ)
                        *(float4*)&g_bnd[((size_t)b * NGRP + g) * SS + 4 * lane] =
                            make_float4(st0, st1, st2, st3);
                }
            }
        } else {
            if (ci + 1 < NCH) copy_chunk_async(sm, b, tid - 32, ci + 1);
        }
        __syncthreads();
    }
}

// =====================================================================
// Kernel 2b (k_dp2): parallel bit recompute. Grid = 32 b x 16 CTAs,
// 256 threads; warp w handles group g = cb*8+w (32 steps) starting from
// the exact boundary vector; writes bits to g_bts.
// =====================================================================
#define DPSTEP3(sv, U) do {                                                      \
    float n3 = fmaxf(st2, st3) + (sv).w;                                         \
    float nsh = __shfl_up_sync(FULLM, n3, 1);                                    \
    float left = (lane == 0) ? 0.0f : left_next;                                 \
    float d1 = st1 - st0;                                                        \
    float d2 = st2 - st1;                                                        \
    float d3 = st3 - st2;                                                        \
    float n1 = fmaxf(st0, st1) + (sv).y;                                         \
    float n2 = fmaxf(st1, st2) + (sv).z;                                         \
    acc1 |= (__float_as_uint(d1) >> (U)) & (1u << (31 - (U)));                   \
    acc2 |= (__float_as_uint(d2) >> (U)) & (1u << (31 - (U)));                   \
    acc3 |= (__float_as_uint(d3) >> (U)) & (1u << (31 - (U)));                   \
    float d0 = st0 - left;                                                       \
    float n0 = fmaxf(left, st0) + (sv).x;                                        \
    acc0 |= (__float_as_uint(d0) >> (U)) & (1u << (31 - (U)));                   \
    st0 = n0; st1 = n1; st2 = n2; st3 = n3; left_next = nsh; } while (0)

#define D2ROW 33   // float4 per (q) row in k_dp2 tile (32 + pad)

__global__ void __launch_bounds__(256, 1)
k_dp2()
{
    extern __shared__ unsigned char smraw[];
    float4* tile = reinterpret_cast<float4*>(smraw);   // [GPW][NQ][D2ROW]

    const int tid = threadIdx.x;
    const int b  = blockIdx.x >> 4;
    const int cb = blockIdx.x & 15;
    const int wid = tid >> 5;
    const int lane = tid & 31;

    // stage sims for the 8 groups (coalesced cp.async)
    for (int i = tid; i < GPW * NQ * GR; i += 256) {
        int w = i / (NQ * GR);
        int rem = i - w * (NQ * GR);
        int q = rem >> 5;
        int r = rem & 31;
        unsigned d = smem_u32(tile + (w * NQ + q) * D2ROW + r);
        const float4* gp = g_simsT + ((size_t)b * NQ + q) * TT
                           + (size_t)(cb * GPW + w) * GR + r;
        asm volatile("cp.async.cg.shared.global [%0], [%1], 16;"
                     :: "r"(d), "l"(gp) : "memory");
    }
    asm volatile("cp.async.commit_group;" ::: "memory");
    asm volatile("cp.async.wait_group 0;" ::: "memory");
    __syncthreads();

    const int g = cb * GPW + wid;
    const int qln = lane < NQ ? lane : NQ - 1;
    const float4* tb = tile + (wid * NQ + qln) * D2ROW;

    float st0, st1, st2, st3, left_next;
    unsigned acc0 = 0, acc1 = 0, acc2 = 0, acc3 = 0;

    if (g == 0) {
        float4 sv = tb[0];
        st0 = sv.x; st1 = sv.y; st2 = sv.z; st3 = sv.w;
        left_next = __shfl_up_sync(FULLM, st3, 1);
#pragma unroll
        for (int u = 1; u < GR; ++u) DPSTEP3(tb[u], u);
    } else {
        float4 bv = *(const float4*)&g_bnd[((size_t)b * NGRP + g) * SS + 4 * qln];
        st0 = bv.x; st1 = bv.y; st2 = bv.z; st3 = bv.w;
        left_next = __shfl_up_sync(FULLM, st3, 1);
#pragma unroll
        for (int u = 0; u < GR; ++u) DPSTEP3(tb[u], u);
    }
    if (lane < NQ)
        *(uint4*)&g_bts[((size_t)b * NGRP + g) * BTROW + lane * 4] =
            make_uint4(acc0, acc1, acc2, acc3);
}

// =====================================================================
// Kernel 3 (k_final): backtrack + segment means + LSTM + head (R10 code)
// =====================================================================
struct SmemF {
    unsigned int bts[NGRP * BTROW];  // 67,584 B
    float zz[SS * BDM];
    int bound[SS + 4];
    float hbuf[HH], cbuf[HH], gates[4 * HH];
    float rbuf[32], r2buf[32];
};

__global__ void __launch_bounds__(256, 1)
k_final(const float* __restrict__ w_ih, const float* __restrict__ w_hh,
        const float* __restrict__ b_ih, const float* __restrict__ b_hh,
        const float* __restrict__ wr1, const float* __restrict__ br1,
        const float* __restrict__ wr2, const float* __restrict__ br2,
        const float* __restrict__ wr3, const float* __restrict__ br3,
        float* __restrict__ out)
{
    extern __shared__ unsigned char smraw[];
    SmemF* sm = reinterpret_cast<SmemF*>(smraw);

    const int tid = threadIdx.x;
    const int b = blockIdx.x;
    const int lane = tid & 31;

    // stage bts (4224 float4) + init
    for (int i = tid; i < NGRP * BTROW / 4; i += 256) {
        unsigned d = smem_u32((float4*)sm->bts + i);
        const float4* gp = (const float4*)(g_bts + (size_t)b * NGRP * BTROW) + i;
        asm volatile("cp.async.cg.shared.global [%0], [%1], 16;"
                     :: "r"(d), "l"(gp) : "memory");
    }
    asm volatile("cp.async.commit_group;" ::: "memory");
    for (int i = tid; i < SS * BDM; i += 256) sm->zz[i] = 0.0f;
    if (tid < HH) { sm->hbuf[tid] = 0.0f; sm->cbuf[tid] = 0.0f; }
    asm volatile("cp.async.wait_group 0;" ::: "memory");
    __syncthreads();

    // ---------------- warp-parallel backtrack ----------------
    if (tid < 32) {
        int s = SS - 1, cur = TT - 1;
        while (s > 0) {
            int col4 = s;
            int gtop = cur >> 5;
            int ttstar = 0;
            for (int gb = gtop - 31; ; gb -= 32) {
                int g = gb + lane;
                unsigned w = 0;
                if (g >= 0 && g <= gtop) {
                    w = sm->bts[g * BTROW + col4];
                    if (g == gtop) {
                        int pm = cur & 31;
                        w &= ~((1u << (31 - pm)) - 1u);
                    }
                }
                unsigned bal = __ballot_sync(FULLM, w != 0);
                if (bal) {
                    int hl = 31 - __clz((int)bal);
                    unsigned wh = __shfl_sync(FULLM, w, hl);
                    int pos = __ffs((int)wh) - 1;
                    ttstar = (gb + hl) * 32 + (31 - pos);
                    break;
                }
                if (gb <= 0 || gb * 32 <= s + 1) break;
            }
            int ttd = ttstar > s ? ttstar : s;
            if (lane == 0) sm->bound[s] = ttd;
            cur = ttd - 1;
            s--;
        }
        if (lane == 0) { sm->bound[0] = 0; sm->bound[SS] = TT; }
    }
    __syncthreads();

    // ---------------- segment sums ----------------
    {
        const int t0 = tid * (TT / 256);
        int lo = 0, hi = SS - 1;
        while (lo < hi) {
            int mid = (lo + hi + 1) >> 1;
            if (sm->bound[mid] <= t0) lo = mid; else hi = mid - 1;
        }
        int s = lo;
        int nxtb = sm->bound[s + 1];
        const float* zb = g_z + ((size_t)b * TT + t0) * BDM;
        float av[BDM];
#pragma unroll
        for (int d = 0; d < BDM; d++) av[d] = 0.0f;

        for (int kk = 0; kk < TT / 256; ++kk) {
            int t = t0 + kk;
            if (t >= nxtb) {
#pragma unroll
                for (int d = 0; d < BDM; d++) {
                    atomicAdd(&sm->zz[s * BDM + d], av[d]);
                    av[d] = 0.0f;
                }
                s++;
                nxtb = sm->bound[s + 1];
            }
#pragma unroll
            for (int d = 0; d < BDM; d++) av[d] += zb[kk * BDM + d];
        }
#pragma unroll
        for (int d = 0; d < BDM; d++) atomicAdd(&sm->zz[s * BDM + d], av[d]);
    }
    __syncthreads();

    for (int i = tid; i < SS * BDM; i += 256) {
        int s = i / BDM;
        sm->zz[i] = sm->zz[i] / (float)(sm->bound[s + 1] - sm->bound[s]);
    }
    __syncthreads();

    // ---------------- LSTM (weights in registers) ----------------
    float whr[HH], wir[BDM], bsr = 0.0f;
    if (tid < 4 * HH) {
#pragma unroll
        for (int kk = 0; kk < HH; kk++) whr[kk] = w_hh[tid * HH + kk];
#pragma unroll
        for (int d = 0; d < BDM; d++) wir[d] = w_ih[tid * BDM + d];
        bsr = b_ih[tid] + b_hh[tid];
    }

    for (int stp = 0; stp < SS; ++stp) {
        if (tid < 4 * HH) {
            float g = bsr;
            const float* xt = sm->zz + stp * BDM;
#pragma unroll
            for (int d = 0; d < BDM; d++) g += wir[d] * xt[d];
#pragma unroll
            for (int kk = 0; kk < HH; kk++) g += whr[kk] * sm->hbuf[kk];
            sm->gates[tid] = g;
        }
        __syncthreads();
        if (tid < HH) {
            float iv = sm->gates[tid];
            float fv = sm->gates[HH + tid];
            float gv = sm->gates[2 * HH + tid];
            float ov = sm->gates[3 * HH + tid];
            float cc = sigm(fv) * sm->cbuf[tid] + sigm(iv) * tanhf(gv);
            sm->cbuf[tid] = cc;
            sm->hbuf[tid] = sigm(ov) * tanhf(cc);
        }
        __syncthreads();
    }

    // ---------------- MLP head ----------------
    if (tid < DD) {
        float r = br1[tid];
#pragma unroll 10
        for (int kk = 0; kk < HH; kk++) r += wr1[tid * HH + kk] * sm->hbuf[kk];
        sm->rbuf[tid] = fmaxf(r, 0.0f);
    }
    __syncthreads();
    if (tid < DD) {
        float r = br2[tid];
#pragma unroll
        for (int kk = 0; kk < DD; kk++) r += wr2[tid * DD + kk] * sm->rbuf[kk];
        sm->r2buf[tid] = fmaxf(r, 0.0f);
    }
    __syncthreads();
    if (tid == 0) {
        float r = br3[0];
#pragma unroll
        for (int d = 0; d < DD; d++) r += wr3[d] * sm->r2buf[d];
        out[b] = r;
    }
}

// =====================================================================
// launch
// =====================================================================
extern "C" void kernel_launch(void* const* d_in, const int* in_sizes, int n_in,
                              void* d_out, int out_size)
{
    (void)in_sizes; (void)n_in; (void)out_size;
    const float* x    = (const float*)d_in[0];
    const float* c    = (const float*)d_in[1];
    const float* w1   = (const float*)d_in[2];
    const float* b1   = (const float*)d_in[3];
    const float* w2   = (const float*)d_in[4];
    const float* b2   = (const float*)d_in[5];
    const float* w3   = (const float*)d_in[6];
    const float* b3   = (const float*)d_in[7];
    const float* w_ih = (const float*)d_in[8];
    const float* w_hh = (const float*)d_in[9];
    const float* b_ih = (const float*)d_in[10];
    const float* b_hh = (const float*)d_in[11];
    const float* wr1  = (const float*)d_in[12];
    const float* br1  = (const float*)d_in[13];
    const float* wr2  = (const float*)d_in[14];
    const float* br2  = (const float*)d_in[15];
    const float* wr3  = (const float*)d_in[16];
    const float* br3  = (const float*)d_in[17];
    float* out = (float*)d_out;

    static int smem_set = 0;
    if (!smem_set) {
        cudaFuncSetAttribute(k_dp1, cudaFuncAttributeMaxDynamicSharedMemorySize,
                             (int)sizeof(SmemD));
        cudaFuncSetAttribute(k_dp2, cudaFuncAttributeMaxDynamicSharedMemorySize,
                             GPW * NQ * D2ROW * 16);
        cudaFuncSetAttribute(k_final, cudaFuncAttributeMaxDynamicSharedMemorySize,
                             (int)sizeof(SmemF));
        smem_set = 1;
    }

    k_project<<<(BB * TT) / 256, 256>>>(x, c, w1, b1, w2, b2, w3, b3);
    k_dp1<<<BB, 256, sizeof(SmemD)>>>();
    k_dp2<<<BB * 16, 256, GPW * NQ * D2ROW * 16>>>();
    k_final<<<BB, 256, sizeof(SmemF)>>>(w_ih, w_hh, b_ih, b_hh,
                                        wr1, br1, wr2, br2, wr3, br3, out);
}